// round 10
// baseline (speedup 1.0000x reference)
#include <cuda_runtime.h>
#include <math.h>

#define NBT  16
#define SLEN 2048
#define HD   64
#define EDIM 256

// Q,K row-major [tok][h] (tf32-rounded). V TRANSPOSED: [bt][h][s] (tf32-rounded).
__device__ float g_q[NBT * SLEN * HD];
__device__ float g_k[NBT * SLEN * HD];
__device__ float g_v[NBT * HD * SLEN];

typedef unsigned int u32;

__device__ __forceinline__ u32 rna_bits(float x) {
    u32 r; asm("cvt.rna.tf32.f32 %0, %1;" : "=r"(r) : "f"(x)); return r;
}
__device__ __forceinline__ float to_tf32(float x) {
    return __uint_as_float(rna_bits(x));
}
__device__ __forceinline__ void cp16(u32 dst, const void* src) {
    asm volatile("cp.async.cg.shared.global [%0], [%1], 16;" :: "r"(dst), "l"(src));
}
__device__ __forceinline__ void cp_commit() { asm volatile("cp.async.commit_group;"); }
__device__ __forceinline__ void cp_wait1()  { asm volatile("cp.async.wait_group 1;"); }
__device__ __forceinline__ void cp_wait0()  { asm volatile("cp.async.wait_group 0;"); }

// m16n8k8 tf32 warp MMA (k-slot order relabeled by caller: slot q -> 2q, slot q+4 -> 2q+1)
__device__ __forceinline__ void mma8(float c[4], const u32 a[4], u32 b0, u32 b1) {
    asm volatile(
        "mma.sync.aligned.m16n8k8.row.col.f32.tf32.tf32.f32 "
        "{%0,%1,%2,%3}, {%4,%5,%6,%7}, {%8,%9}, {%0,%1,%2,%3};"
        : "+f"(c[0]), "+f"(c[1]), "+f"(c[2]), "+f"(c[3])
        : "r"(a[0]), "r"(a[1]), "r"(a[2]), "r"(a[3]), "r"(b0), "r"(b1));
}

// ---------------------------------------------------------------------------
// Kernel 1: QKV projection via warp MMA (tf32, x hi/lo split). Unchanged (R9).
// ---------------------------------------------------------------------------
#define PXS_OFF 0
#define PXS_BUF 9216
#define PWS_OFF 18432
#define PWS_W   4608
#define PBS_OFF 32256
#define PROJ_FLOATS 32448   // 129.8 KB

__global__ __launch_bounds__(256) void qkv_proj_mma(
    const float* __restrict__ x,
    const float* __restrict__ Wq, const float* __restrict__ bq,
    const float* __restrict__ Wk, const float* __restrict__ bk,
    const float* __restrict__ Wv, const float* __restrict__ bv)
{
    extern __shared__ float sm[];
    const u32 sb = (u32)__cvta_generic_to_shared(sm);
    float* bs = sm + PBS_OFF;

    const int tid  = threadIdx.x;
    const int wid  = tid >> 5;
    const int lane = tid & 31;
    const int g    = lane >> 2;
    const int q    = lane & 3;
    const int t0   = blockIdx.x * 128;

    const float* Wmat[3] = {Wq, Wk, Wv};

    if (tid < 64) { bs[tid] = bq[tid]; bs[64 + tid] = bk[tid]; bs[128 + tid] = bv[tid]; }

    for (int i = tid; i < 2048; i += 256) {
        int r = i >> 4, c = i & 15;
        cp16(sb + (PXS_OFF + r * 72 + c * 4) * 4, x + (size_t)(t0 + r) * EDIM + c * 4);
    }
    cp_commit();

    float cc[3][8][4];
    #pragma unroll
    for (int w = 0; w < 3; w++)
        #pragma unroll
        for (int nb = 0; nb < 8; nb++)
            #pragma unroll
            for (int j = 0; j < 4; j++) cc[w][nb][j] = 0.f;

    const int rowA = wid * 16 + g;

    for (int ch = 0; ch < 4; ch++) {
        const int buf = ch & 1;
        __syncthreads();

        if (ch + 1 < 4) {
            const int nbuf = buf ^ 1;
            for (int i = tid; i < 2048; i += 256) {
                int r = i >> 4, c = i & 15;
                cp16(sb + (PXS_OFF + nbuf * PXS_BUF + r * 72 + c * 4) * 4,
                     x + (size_t)(t0 + r) * EDIM + (ch + 1) * 64 + c * 4);
            }
            cp_commit();
        }

        for (int i = tid; i < 3072; i += 256) {
            int w = i >> 10, rem = i & 1023;
            int go = rem >> 4, c4 = rem & 15;
            float4 v = *(const float4*)(Wmat[w] + go * EDIM + ch * 64 + c4 * 4);
            float4 o;
            o.x = to_tf32(v.x); o.y = to_tf32(v.y);
            o.z = to_tf32(v.z); o.w = to_tf32(v.w);
            *(float4*)(sm + PWS_OFF + w * PWS_W + go * 72 + c4 * 4) = o;
        }

        if (ch + 1 < 4) cp_wait1(); else cp_wait0();
        __syncthreads();

        const float* xb = sm + PXS_OFF + buf * PXS_BUF;
        #pragma unroll
        for (int kc = 0; kc < 8; kc++) {
            float2 ra0 = *(const float2*)(xb + rowA * 72 + kc * 8 + 2 * q);
            float2 ra1 = *(const float2*)(xb + (rowA + 8) * 72 + kc * 8 + 2 * q);
            u32 ah[4], al[4];
            ah[0] = rna_bits(ra0.x); ah[1] = rna_bits(ra1.x);
            ah[2] = rna_bits(ra0.y); ah[3] = rna_bits(ra1.y);
            al[0] = rna_bits(ra0.x - __uint_as_float(ah[0]));
            al[1] = rna_bits(ra1.x - __uint_as_float(ah[1]));
            al[2] = rna_bits(ra0.y - __uint_as_float(ah[2]));
            al[3] = rna_bits(ra1.y - __uint_as_float(ah[3]));

            #pragma unroll
            for (int w = 0; w < 3; w++) {
                const float* wb = sm + PWS_OFF + w * PWS_W;
                u32 bb[8][2];
                #pragma unroll
                for (int nb = 0; nb < 8; nb++) {
                    float2 b = *(const float2*)(wb + (nb * 8 + g) * 72 + kc * 8 + 2 * q);
                    bb[nb][0] = __float_as_uint(b.x);
                    bb[nb][1] = __float_as_uint(b.y);
                    mma8(cc[w][nb], ah, bb[nb][0], bb[nb][1]);
                }
                #pragma unroll
                for (int nb = 0; nb < 8; nb++)
                    mma8(cc[w][nb], al, bb[nb][0], bb[nb][1]);
            }
        }
    }

    const int tok0 = t0 + rowA;
    const int bt   = tok0 >> 11;
    const int sl   = tok0 & 2047;
    float* vt = g_v + (size_t)bt * HD * SLEN;

    #pragma unroll
    for (int w = 0; w < 3; w++) {
        #pragma unroll
        for (int nb = 0; nb < 8; nb++) {
            const int h0 = nb * 8 + 2 * q;
            float c0 = to_tf32(cc[w][nb][0] + bs[w * 64 + h0]);
            float c1 = to_tf32(cc[w][nb][1] + bs[w * 64 + h0 + 1]);
            float c2 = to_tf32(cc[w][nb][2] + bs[w * 64 + h0]);
            float c3 = to_tf32(cc[w][nb][3] + bs[w * 64 + h0 + 1]);
            if (w < 2) {
                float* ob = (w == 0 ? g_q : g_k);
                float2 v0; v0.x = c0; v0.y = c1;
                float2 v1; v1.x = c2; v1.y = c3;
                *(float2*)(ob + (size_t)tok0 * HD + h0) = v0;
                *(float2*)(ob + (size_t)(tok0 + 8) * HD + h0) = v1;
            } else {
                vt[(size_t)h0 * SLEN + sl]           = c0;
                vt[(size_t)(h0 + 1) * SLEN + sl]     = c1;
                vt[(size_t)h0 * SLEN + sl + 8]       = c2;
                vt[(size_t)(h0 + 1) * SLEN + sl + 8] = c3;
            }
        }
    }
}

// ---------------------------------------------------------------------------
// Kernel 2: warp-MMA tf32 flash attention + fused Wo.
// CTA = 128 queries, 4 warps, M=32 per warp (2 row-blocks of 16).
// P and O never touch smem: C-frag == A-frag under k-relabeling (reg permute).
// ---------------------------------------------------------------------------
#define KS_OFF 0
#define KSTRIDE 72
#define KBUF 4608
#define VS_OFF 9216
#define VSTRIDE 72
#define VBUF 4608
#define WO_OFF 18432
#define BO_OFF 23040
#define ATTN_FLOATS 23104   // 92.4 KB

#define SCALE 0.0625f

__global__ __launch_bounds__(128) void attn_mma_kernel(
    const u32* __restrict__ mask,
    const float* __restrict__ Wo, const float* __restrict__ bo,
    float* __restrict__ out)
{
    extern __shared__ float sm[];
    float* Ks  = sm + KS_OFF;
    float* Vs  = sm + VS_OFF;
    float* Wos = sm + WO_OFF;
    float* bos = sm + BO_OFF;
    const u32 sb = (u32)__cvta_generic_to_shared(sm);

    const int tid  = threadIdx.x;
    const int wid  = tid >> 5;    // 0..3
    const int lane = tid & 31;
    const int g    = lane >> 2;
    const int q    = lane & 3;
    const int bt   = blockIdx.y;
    const int q0   = blockIdx.x * 128;

    const int r00 = wid * 32 + g;            // rb0 rows: r00, r00+8; rb1: +16, +24
    const size_t qgbase = (size_t)bt * SLEN + q0 + r00;

    const float* kbase  = g_k + ((size_t)bt * SLEN) * HD;
    const float* vtbase = g_v + (size_t)bt * HD * SLEN;

    // Q A-fragments for both row-blocks (resident)
    u32 qa[2][8][4];
    #pragma unroll
    for (int rb = 0; rb < 2; rb++) {
        const float* qr0 = g_q + (qgbase + rb * 16) * HD;
        const float* qr1 = g_q + (qgbase + rb * 16 + 8) * HD;
        #pragma unroll
        for (int kc = 0; kc < 8; kc++) {
            float2 f0 = __ldg((const float2*)(qr0 + kc * 8 + 2 * q));
            float2 f1 = __ldg((const float2*)(qr1 + kc * 8 + 2 * q));
            qa[rb][kc][0] = __float_as_uint(f0.x);
            qa[rb][kc][1] = __float_as_uint(f1.x);
            qa[rb][kc][2] = __float_as_uint(f0.y);
            qa[rb][kc][3] = __float_as_uint(f1.y);
        }
    }

    // stage tile 0
    for (int i = tid; i < 1024; i += 128) {
        int r = i >> 4, c = i & 15;
        cp16(sb + (KS_OFF + r * KSTRIDE + c * 4) * 4, kbase + (size_t)r * HD + c * 4);
        cp16(sb + (VS_OFF + r * VSTRIDE + c * 4) * 4, vtbase + (size_t)r * SLEN + c * 4);
    }
    cp_commit();

    // stage Wo (tf32) + bo once (epilogue-only region)
    for (int i = tid; i < 4096; i += 128) {
        int go = i >> 6, h = i & 63;
        Wos[go * KSTRIDE + h] = to_tf32(Wo[i]);
    }
    if (tid < 64) bos[tid] = bo[tid];

    float oc[2][8][4];
    #pragma unroll
    for (int rb = 0; rb < 2; rb++)
        #pragma unroll
        for (int nb = 0; nb < 8; nb++)
            #pragma unroll
            for (int j = 0; j < 4; j++) oc[rb][nb][j] = 0.f;
    float lr[4] = {0.f, 0.f, 0.f, 0.f};   // rows r00, +8, +16, +24

    const u32* mr0 = mask + qgbase * SLEN;
    const u32* mr1 = mask + (qgbase + 8) * SLEN;
    const u32* mr2 = mask + (qgbase + 16) * SLEN;
    const u32* mr3 = mask + (qgbase + 24) * SLEN;

    for (int kb = 0; kb < 32; kb++) {
        const int buf = kb & 1;
        __syncthreads();   // all reads of buf^1 (tile kb-1) complete

        if (kb + 1 < 32) {
            const int nbuf = buf ^ 1;
            const size_t kg1 = (size_t)(kb + 1) * 64;
            for (int i = tid; i < 1024; i += 128) {
                int r = i >> 4, c = i & 15;
                cp16(sb + (KS_OFF + nbuf * KBUF + r * KSTRIDE + c * 4) * 4,
                     kbase + (kg1 + r) * HD + c * 4);
                cp16(sb + (VS_OFF + nbuf * VBUF + r * VSTRIDE + c * 4) * 4,
                     vtbase + (size_t)r * SLEN + kg1 + c * 4);
            }
            cp_commit();
            cp_wait1();
        } else {
            cp_wait0();
        }
        __syncthreads();

        // ---- S = Q K^T : each B-frag feeds both row-blocks ----
        const float* Kb = Ks + buf * KBUF;
        float sc[2][8][4];
        #pragma unroll
        for (int rb = 0; rb < 2; rb++)
            #pragma unroll
            for (int nb = 0; nb < 8; nb++)
                #pragma unroll
                for (int j = 0; j < 4; j++) sc[rb][nb][j] = 0.f;

        #pragma unroll
        for (int kc = 0; kc < 8; kc++) {
            #pragma unroll
            for (int nb = 0; nb < 8; nb++) {
                float2 b = *(const float2*)(Kb + (nb * 8 + g) * KSTRIDE + kc * 8 + 2 * q);
                const u32 b0 = __float_as_uint(b.x), b1 = __float_as_uint(b.y);
                mma8(sc[0][nb], qa[0][kc], b0, b1);
                mma8(sc[1][nb], qa[1][kc], b0, b1);
            }
        }

        // ---- softmax + permute C-frag -> PV A-frag IN REGISTERS ----
        const int kcol = kb * 64;
        u32 pa[2][8][4];
        #pragma unroll
        for (int nb = 0; nb < 8; nb++) {
            const int mc = kcol + nb * 8 + 2 * q;
            uint2 m0 = __ldg((const uint2*)(mr0 + mc));
            uint2 m1 = __ldg((const uint2*)(mr1 + mc));
            uint2 m2 = __ldg((const uint2*)(mr2 + mc));
            uint2 m3 = __ldg((const uint2*)(mr3 + mc));
            // rb0: c0,c1 row r00; c2,c3 row r00+8
            float p00 = m0.x ? 0.f : to_tf32(__expf(sc[0][nb][0] * SCALE));
            float p01 = m0.y ? 0.f : to_tf32(__expf(sc[0][nb][1] * SCALE));
            float p02 = m1.x ? 0.f : to_tf32(__expf(sc[0][nb][2] * SCALE));
            float p03 = m1.y ? 0.f : to_tf32(__expf(sc[0][nb][3] * SCALE));
            lr[0] += p00 + p01; lr[1] += p02 + p03;
            pa[0][nb][0] = __float_as_uint(p00);   // a0 = c0
            pa[0][nb][1] = __float_as_uint(p02);   // a1 = c2
            pa[0][nb][2] = __float_as_uint(p01);   // a2 = c1
            pa[0][nb][3] = __float_as_uint(p03);   // a3 = c3
            // rb1
            float p10 = m2.x ? 0.f : to_tf32(__expf(sc[1][nb][0] * SCALE));
            float p11 = m2.y ? 0.f : to_tf32(__expf(sc[1][nb][1] * SCALE));
            float p12 = m3.x ? 0.f : to_tf32(__expf(sc[1][nb][2] * SCALE));
            float p13 = m3.y ? 0.f : to_tf32(__expf(sc[1][nb][3] * SCALE));
            lr[2] += p10 + p11; lr[3] += p12 + p13;
            pa[1][nb][0] = __float_as_uint(p10);
            pa[1][nb][1] = __float_as_uint(p12);
            pa[1][nb][2] = __float_as_uint(p11);
            pa[1][nb][3] = __float_as_uint(p13);
        }

        // ---- O += P V : B-frags from transposed V, shared across row-blocks ----
        const float* Vb = Vs + buf * VBUF;
        #pragma unroll
        for (int kc = 0; kc < 8; kc++) {
            #pragma unroll
            for (int nb = 0; nb < 8; nb++) {
                float2 b = *(const float2*)(Vb + (nb * 8 + g) * VSTRIDE + kc * 8 + 2 * q);
                const u32 b0 = __float_as_uint(b.x), b1 = __float_as_uint(b.y);
                mma8(oc[0][nb], pa[0][kc], b0, b1);
                mma8(oc[1][nb], pa[1][kc], b0, b1);
            }
        }
    }

    // ---- reduce l over the quad (cols), normalize, O C-frag -> Wo A-frag ----
    #pragma unroll
    for (int j = 0; j < 4; j++) {
        lr[j] += __shfl_xor_sync(0xffffffffu, lr[j], 1);
        lr[j] += __shfl_xor_sync(0xffffffffu, lr[j], 2);
    }
    const float inv[4] = {1.f / lr[0], 1.f / lr[1], 1.f / lr[2], 1.f / lr[3]};

    u32 oa[2][8][4];
    #pragma unroll
    for (int rb = 0; rb < 2; rb++) {
        const float i0 = inv[rb * 2], i1 = inv[rb * 2 + 1];
        #pragma unroll
        for (int nb = 0; nb < 8; nb++) {
            oa[rb][nb][0] = rna_bits(oc[rb][nb][0] * i0);   // a0 = c0
            oa[rb][nb][1] = rna_bits(oc[rb][nb][2] * i1);   // a1 = c2
            oa[rb][nb][2] = rna_bits(oc[rb][nb][1] * i0);   // a2 = c1
            oa[rb][nb][3] = rna_bits(oc[rb][nb][3] * i1);   // a3 = c3
        }
    }

    // ---- out = O_norm @ Wo^T + bo ----
    float rc[2][8][4];
    #pragma unroll
    for (int rb = 0; rb < 2; rb++)
        #pragma unroll
        for (int nb = 0; nb < 8; nb++)
            #pragma unroll
            for (int j = 0; j < 4; j++) rc[rb][nb][j] = 0.f;
    #pragma unroll
    for (int kc = 0; kc < 8; kc++) {
        #pragma unroll
        for (int nb = 0; nb < 8; nb++) {
            float2 b = *(const float2*)(Wos + (nb * 8 + g) * KSTRIDE + kc * 8 + 2 * q);
            const u32 b0 = __float_as_uint(b.x), b1 = __float_as_uint(b.y);
            mma8(rc[0][nb], oa[0][kc], b0, b1);
            mma8(rc[1][nb], oa[1][kc], b0, b1);
        }
    }

    #pragma unroll
    for (int rb = 0; rb < 2; rb++) {
        float* o0 = out + (qgbase + rb * 16) * HD;
        float* o1 = out + (qgbase + rb * 16 + 8) * HD;
        #pragma unroll
        for (int nb = 0; nb < 8; nb++) {
            const int col = nb * 8 + 2 * q;
            float2 w0, w1;
            w0.x = rc[rb][nb][0] + bos[col];  w0.y = rc[rb][nb][1] + bos[col + 1];
            w1.x = rc[rb][nb][2] + bos[col];  w1.y = rc[rb][nb][3] + bos[col + 1];
            *(float2*)(o0 + col) = w0;
            *(float2*)(o1 + col) = w1;
        }
    }
}

// ---------------------------------------------------------------------------
extern "C" void kernel_launch(void* const* d_in, const int* in_sizes, int n_in,
                              void* d_out, int out_size)
{
    const float* x    = (const float*)d_in[0];
    const u32*   mask = (const u32*)d_in[1];
    const float* Wq   = (const float*)d_in[2];
    const float* bq   = (const float*)d_in[3];
    const float* Wk   = (const float*)d_in[4];
    const float* bk   = (const float*)d_in[5];
    const float* Wv   = (const float*)d_in[6];
    const float* bv   = (const float*)d_in[7];
    const float* Wo   = (const float*)d_in[8];
    const float* bo   = (const float*)d_in[9];
    float*       out  = (float*)d_out;

    const int proj_smem = PROJ_FLOATS * (int)sizeof(float);   // 129.8 KB
    const int attn_smem = ATTN_FLOATS * (int)sizeof(float);   // 92.4 KB

    cudaFuncSetAttribute(qkv_proj_mma,
                         cudaFuncAttributeMaxDynamicSharedMemorySize, proj_smem);
    cudaFuncSetAttribute(attn_mma_kernel,
                         cudaFuncAttributeMaxDynamicSharedMemorySize, attn_smem);

    qkv_proj_mma<<<256, 256, proj_smem>>>(x, Wq, bq, Wk, bk, Wv, bv);
    attn_mma_kernel<<<dim3(16, 16), 128, attn_smem>>>(mask, Wo, bo, out);
}

// round 11
// speedup vs baseline: 1.1967x; 1.1967x over previous
#include <cuda_runtime.h>
#include <math.h>

#define NBT  16
#define SLEN 2048
#define HD   64
#define EDIM 256

// Q,K row-major [tok][h] (tf32-rounded). V TRANSPOSED: [bt][h][s] (tf32-rounded).
__device__ float g_q[NBT * SLEN * HD];
__device__ float g_k[NBT * SLEN * HD];
__device__ float g_v[NBT * HD * SLEN];

typedef unsigned int u32;

__device__ __forceinline__ u32 rna_bits(float x) {
    u32 r; asm("cvt.rna.tf32.f32 %0, %1;" : "=r"(r) : "f"(x)); return r;
}
__device__ __forceinline__ float to_tf32(float x) {
    return __uint_as_float(rna_bits(x));
}
__device__ __forceinline__ void cp16(u32 dst, const void* src) {
    asm volatile("cp.async.cg.shared.global [%0], [%1], 16;" :: "r"(dst), "l"(src));
}
__device__ __forceinline__ void cp_commit() { asm volatile("cp.async.commit_group;"); }
__device__ __forceinline__ void cp_wait1()  { asm volatile("cp.async.wait_group 1;"); }
__device__ __forceinline__ void cp_wait0()  { asm volatile("cp.async.wait_group 0;"); }

// m16n8k8 tf32 warp MMA (k-slot order relabeled by caller: slot q -> 2q, slot q+4 -> 2q+1)
__device__ __forceinline__ void mma8(float c[4], const u32 a[4], u32 b0, u32 b1) {
    asm volatile(
        "mma.sync.aligned.m16n8k8.row.col.f32.tf32.tf32.f32 "
        "{%0,%1,%2,%3}, {%4,%5,%6,%7}, {%8,%9}, {%0,%1,%2,%3};"
        : "+f"(c[0]), "+f"(c[1]), "+f"(c[2]), "+f"(c[3])
        : "r"(a[0]), "r"(a[1]), "r"(a[2]), "r"(a[3]), "r"(b0), "r"(b1));
}

// ---------------------------------------------------------------------------
// Kernel 1: QKV projection via warp MMA (tf32, x hi/lo split). Unchanged (R9).
// ---------------------------------------------------------------------------
#define PXS_OFF 0
#define PXS_BUF 9216
#define PWS_OFF 18432
#define PWS_W   4608
#define PBS_OFF 32256
#define PROJ_FLOATS 32448   // 129.8 KB

__global__ __launch_bounds__(256) void qkv_proj_mma(
    const float* __restrict__ x,
    const float* __restrict__ Wq, const float* __restrict__ bq,
    const float* __restrict__ Wk, const float* __restrict__ bk,
    const float* __restrict__ Wv, const float* __restrict__ bv)
{
    extern __shared__ float sm[];
    const u32 sb = (u32)__cvta_generic_to_shared(sm);
    float* bs = sm + PBS_OFF;

    const int tid  = threadIdx.x;
    const int wid  = tid >> 5;
    const int lane = tid & 31;
    const int g    = lane >> 2;
    const int q    = lane & 3;
    const int t0   = blockIdx.x * 128;

    const float* Wmat[3] = {Wq, Wk, Wv};

    if (tid < 64) { bs[tid] = bq[tid]; bs[64 + tid] = bk[tid]; bs[128 + tid] = bv[tid]; }

    for (int i = tid; i < 2048; i += 256) {
        int r = i >> 4, c = i & 15;
        cp16(sb + (PXS_OFF + r * 72 + c * 4) * 4, x + (size_t)(t0 + r) * EDIM + c * 4);
    }
    cp_commit();

    float cc[3][8][4];
    #pragma unroll
    for (int w = 0; w < 3; w++)
        #pragma unroll
        for (int nb = 0; nb < 8; nb++)
            #pragma unroll
            for (int j = 0; j < 4; j++) cc[w][nb][j] = 0.f;

    const int rowA = wid * 16 + g;

    for (int ch = 0; ch < 4; ch++) {
        const int buf = ch & 1;
        __syncthreads();

        if (ch + 1 < 4) {
            const int nbuf = buf ^ 1;
            for (int i = tid; i < 2048; i += 256) {
                int r = i >> 4, c = i & 15;
                cp16(sb + (PXS_OFF + nbuf * PXS_BUF + r * 72 + c * 4) * 4,
                     x + (size_t)(t0 + r) * EDIM + (ch + 1) * 64 + c * 4);
            }
            cp_commit();
        }

        for (int i = tid; i < 3072; i += 256) {
            int w = i >> 10, rem = i & 1023;
            int go = rem >> 4, c4 = rem & 15;
            float4 v = *(const float4*)(Wmat[w] + go * EDIM + ch * 64 + c4 * 4);
            float4 o;
            o.x = to_tf32(v.x); o.y = to_tf32(v.y);
            o.z = to_tf32(v.z); o.w = to_tf32(v.w);
            *(float4*)(sm + PWS_OFF + w * PWS_W + go * 72 + c4 * 4) = o;
        }

        if (ch + 1 < 4) cp_wait1(); else cp_wait0();
        __syncthreads();

        const float* xb = sm + PXS_OFF + buf * PXS_BUF;
        #pragma unroll
        for (int kc = 0; kc < 8; kc++) {
            float2 ra0 = *(const float2*)(xb + rowA * 72 + kc * 8 + 2 * q);
            float2 ra1 = *(const float2*)(xb + (rowA + 8) * 72 + kc * 8 + 2 * q);
            u32 ah[4], al[4];
            ah[0] = rna_bits(ra0.x); ah[1] = rna_bits(ra1.x);
            ah[2] = rna_bits(ra0.y); ah[3] = rna_bits(ra1.y);
            al[0] = rna_bits(ra0.x - __uint_as_float(ah[0]));
            al[1] = rna_bits(ra1.x - __uint_as_float(ah[1]));
            al[2] = rna_bits(ra0.y - __uint_as_float(ah[2]));
            al[3] = rna_bits(ra1.y - __uint_as_float(ah[3]));

            #pragma unroll
            for (int w = 0; w < 3; w++) {
                const float* wb = sm + PWS_OFF + w * PWS_W;
                u32 bb[8][2];
                #pragma unroll
                for (int nb = 0; nb < 8; nb++) {
                    float2 b = *(const float2*)(wb + (nb * 8 + g) * 72 + kc * 8 + 2 * q);
                    bb[nb][0] = __float_as_uint(b.x);
                    bb[nb][1] = __float_as_uint(b.y);
                    mma8(cc[w][nb], ah, bb[nb][0], bb[nb][1]);
                }
                #pragma unroll
                for (int nb = 0; nb < 8; nb++)
                    mma8(cc[w][nb], al, bb[nb][0], bb[nb][1]);
            }
        }
    }

    const int tok0 = t0 + rowA;
    const int bt   = tok0 >> 11;
    const int sl   = tok0 & 2047;
    float* vt = g_v + (size_t)bt * HD * SLEN;

    #pragma unroll
    for (int w = 0; w < 3; w++) {
        #pragma unroll
        for (int nb = 0; nb < 8; nb++) {
            const int h0 = nb * 8 + 2 * q;
            float c0 = to_tf32(cc[w][nb][0] + bs[w * 64 + h0]);
            float c1 = to_tf32(cc[w][nb][1] + bs[w * 64 + h0 + 1]);
            float c2 = to_tf32(cc[w][nb][2] + bs[w * 64 + h0]);
            float c3 = to_tf32(cc[w][nb][3] + bs[w * 64 + h0 + 1]);
            if (w < 2) {
                float* ob = (w == 0 ? g_q : g_k);
                float2 v0; v0.x = c0; v0.y = c1;
                float2 v1; v1.x = c2; v1.y = c3;
                *(float2*)(ob + (size_t)tok0 * HD + h0) = v0;
                *(float2*)(ob + (size_t)(tok0 + 8) * HD + h0) = v1;
            } else {
                vt[(size_t)h0 * SLEN + sl]           = c0;
                vt[(size_t)(h0 + 1) * SLEN + sl]     = c1;
                vt[(size_t)h0 * SLEN + sl + 8]       = c2;
                vt[(size_t)(h0 + 1) * SLEN + sl + 8] = c3;
            }
        }
    }
}

// ---------------------------------------------------------------------------
// Kernel 2: warp-MMA tf32 flash attention + fused Wo.
// CTA = 128 queries, 8 warps, M=16 per warp (R9 shape), but P and O stay in
// registers via C-frag -> A-frag permute (R10 trick, correctness-validated).
// ---------------------------------------------------------------------------
#define KS_OFF 0
#define KSTRIDE 72
#define KBUF 4608
#define VS_OFF 9216
#define VSTRIDE 72
#define VBUF 4608
#define BO_OFF 18432
#define ATTN_FLOATS 18496   // 74.0 KB  -> 2 CTAs/SM (reg-capped at 128)

#define SCALE 0.0625f

__global__ __launch_bounds__(256, 2) void attn_mma_kernel(
    const u32* __restrict__ mask,
    const float* __restrict__ Wo, const float* __restrict__ bo,
    float* __restrict__ out)
{
    extern __shared__ float sm[];
    float* Ks  = sm + KS_OFF;
    float* Vs  = sm + VS_OFF;
    float* bos = sm + BO_OFF;
    const u32 sb = (u32)__cvta_generic_to_shared(sm);

    const int tid  = threadIdx.x;
    const int wid  = tid >> 5;
    const int lane = tid & 31;
    const int g    = lane >> 2;
    const int q    = lane & 3;
    const int bt   = blockIdx.y;
    const int q0   = blockIdx.x * 128;

    const int r0 = wid * 16 + g;
    const size_t qg0 = (size_t)bt * SLEN + q0 + r0;
    const size_t qg1 = qg0 + 8;

    const float* kbase  = g_k + ((size_t)bt * SLEN) * HD;
    const float* vtbase = g_v + (size_t)bt * HD * SLEN;

    // Q A-fragments (relabeled slots), resident
    u32 qa[8][4];
    {
        const float* qr0 = g_q + qg0 * HD;
        const float* qr1 = g_q + qg1 * HD;
        #pragma unroll
        for (int kc = 0; kc < 8; kc++) {
            float2 f0 = __ldg((const float2*)(qr0 + kc * 8 + 2 * q));
            float2 f1 = __ldg((const float2*)(qr1 + kc * 8 + 2 * q));
            qa[kc][0] = __float_as_uint(f0.x);
            qa[kc][1] = __float_as_uint(f1.x);
            qa[kc][2] = __float_as_uint(f0.y);
            qa[kc][3] = __float_as_uint(f1.y);
        }
    }

    // stage tile 0: K natural [s][h], V transposed [h][s]
    for (int i = tid; i < 1024; i += 256) {
        int r = i >> 4, c = i & 15;
        cp16(sb + (KS_OFF + r * KSTRIDE + c * 4) * 4, kbase + (size_t)r * HD + c * 4);
        cp16(sb + (VS_OFF + r * VSTRIDE + c * 4) * 4, vtbase + (size_t)r * SLEN + c * 4);
    }
    cp_commit();

    if (tid < 64) bos[tid] = bo[tid];

    float oc[8][4];
    #pragma unroll
    for (int nb = 0; nb < 8; nb++)
        #pragma unroll
        for (int j = 0; j < 4; j++) oc[nb][j] = 0.f;
    float l0 = 0.f, l1 = 0.f;

    const u32* mr0 = mask + qg0 * SLEN;
    const u32* mr1 = mask + qg1 * SLEN;

    for (int kb = 0; kb < 32; kb++) {
        const int buf = kb & 1;
        __syncthreads();   // all reads of buf^1 (tile kb-1) complete

        if (kb + 1 < 32) {
            const int nbuf = buf ^ 1;
            const size_t kg1 = (size_t)(kb + 1) * 64;
            for (int i = tid; i < 1024; i += 256) {
                int r = i >> 4, c = i & 15;
                cp16(sb + (KS_OFF + nbuf * KBUF + r * KSTRIDE + c * 4) * 4,
                     kbase + (kg1 + r) * HD + c * 4);
                cp16(sb + (VS_OFF + nbuf * VBUF + r * VSTRIDE + c * 4) * 4,
                     vtbase + (size_t)r * SLEN + kg1 + c * 4);
            }
            cp_commit();
            cp_wait1();
        } else {
            cp_wait0();
        }
        __syncthreads();

        // ---- S = Q K^T ----
        const float* Kb = Ks + buf * KBUF;
        float sc[8][4];
        #pragma unroll
        for (int nb = 0; nb < 8; nb++)
            #pragma unroll
            for (int j = 0; j < 4; j++) sc[nb][j] = 0.f;

        #pragma unroll
        for (int kc = 0; kc < 8; kc++) {
            #pragma unroll
            for (int nb = 0; nb < 8; nb++) {
                float2 b = *(const float2*)(Kb + (nb * 8 + g) * KSTRIDE + kc * 8 + 2 * q);
                mma8(sc[nb], qa[kc], __float_as_uint(b.x), __float_as_uint(b.y));
            }
        }

        // ---- softmax + C-frag -> A-frag permute IN REGISTERS ----
        const int kcol = kb * 64;
        u32 pa[8][4];
        #pragma unroll
        for (int nb = 0; nb < 8; nb++) {
            const int mc = kcol + nb * 8 + 2 * q;
            uint2 m0 = __ldg((const uint2*)(mr0 + mc));
            uint2 m1 = __ldg((const uint2*)(mr1 + mc));
            float p0 = m0.x ? 0.f : to_tf32(__expf(sc[nb][0] * SCALE));
            float p1 = m0.y ? 0.f : to_tf32(__expf(sc[nb][1] * SCALE));
            float p2 = m1.x ? 0.f : to_tf32(__expf(sc[nb][2] * SCALE));
            float p3 = m1.y ? 0.f : to_tf32(__expf(sc[nb][3] * SCALE));
            l0 += p0 + p1;
            l1 += p2 + p3;
            pa[nb][0] = __float_as_uint(p0);   // a0 = c0
            pa[nb][1] = __float_as_uint(p2);   // a1 = c2
            pa[nb][2] = __float_as_uint(p1);   // a2 = c1
            pa[nb][3] = __float_as_uint(p3);   // a3 = c3
        }

        // ---- O += P V ----
        const float* Vb = Vs + buf * VBUF;
        #pragma unroll
        for (int kc = 0; kc < 8; kc++) {
            #pragma unroll
            for (int nb = 0; nb < 8; nb++) {
                float2 b = *(const float2*)(Vb + (nb * 8 + g) * VSTRIDE + kc * 8 + 2 * q);
                mma8(oc[nb], pa[kc], __float_as_uint(b.x), __float_as_uint(b.y));
            }
        }
    }

    // ---- reduce l over quad, normalize, O C-frag -> Wo A-frag (registers) ----
    l0 += __shfl_xor_sync(0xffffffffu, l0, 1);
    l0 += __shfl_xor_sync(0xffffffffu, l0, 2);
    l1 += __shfl_xor_sync(0xffffffffu, l1, 1);
    l1 += __shfl_xor_sync(0xffffffffu, l1, 2);
    const float inv0 = 1.0f / l0;
    const float inv1 = 1.0f / l1;

    u32 oa[8][4];
    #pragma unroll
    for (int nb = 0; nb < 8; nb++) {
        oa[nb][0] = rna_bits(oc[nb][0] * inv0);   // a0 = c0
        oa[nb][1] = rna_bits(oc[nb][2] * inv1);   // a1 = c2
        oa[nb][2] = rna_bits(oc[nb][1] * inv0);   // a2 = c1
        oa[nb][3] = rna_bits(oc[nb][3] * inv1);   // a3 = c3
    }
    __syncthreads();   // everyone done with K/V tiles

    // ---- stage Wo (RNA) into Ks area, stride 72 ----
    for (int i = tid; i < 4096; i += 256) {
        int go = i >> 6, h = i & 63;
        Ks[go * KSTRIDE + h] = to_tf32(Wo[i]);
    }
    __syncthreads();

    // ---- out = O_norm @ Wo^T + bo ----
    float rc[8][4];
    #pragma unroll
    for (int nb = 0; nb < 8; nb++)
        #pragma unroll
        for (int j = 0; j < 4; j++) rc[nb][j] = 0.f;
    #pragma unroll
    for (int kc = 0; kc < 8; kc++) {
        #pragma unroll
        for (int nb = 0; nb < 8; nb++) {
            float2 b = *(const float2*)(Ks + (nb * 8 + g) * KSTRIDE + kc * 8 + 2 * q);
            mma8(rc[nb], oa[kc], __float_as_uint(b.x), __float_as_uint(b.y));
        }
    }

    float* o0 = out + qg0 * HD;
    float* o1 = out + qg1 * HD;
    #pragma unroll
    for (int nb = 0; nb < 8; nb++) {
        const int col = nb * 8 + 2 * q;
        float2 w0, w1;
        w0.x = rc[nb][0] + bos[col];     w0.y = rc[nb][1] + bos[col + 1];
        w1.x = rc[nb][2] + bos[col];     w1.y = rc[nb][3] + bos[col + 1];
        *(float2*)(o0 + col) = w0;
        *(float2*)(o1 + col) = w1;
    }
}

// ---------------------------------------------------------------------------
extern "C" void kernel_launch(void* const* d_in, const int* in_sizes, int n_in,
                              void* d_out, int out_size)
{
    const float* x    = (const float*)d_in[0];
    const u32*   mask = (const u32*)d_in[1];
    const float* Wq   = (const float*)d_in[2];
    const float* bq   = (const float*)d_in[3];
    const float* Wk   = (const float*)d_in[4];
    const float* bk   = (const float*)d_in[5];
    const float* Wv   = (const float*)d_in[6];
    const float* bv   = (const float*)d_in[7];
    const float* Wo   = (const float*)d_in[8];
    const float* bo   = (const float*)d_in[9];
    float*       out  = (float*)d_out;

    const int proj_smem = PROJ_FLOATS * (int)sizeof(float);   // 129.8 KB
    const int attn_smem = ATTN_FLOATS * (int)sizeof(float);   // 74.0 KB

    cudaFuncSetAttribute(qkv_proj_mma,
                         cudaFuncAttributeMaxDynamicSharedMemorySize, proj_smem);
    cudaFuncSetAttribute(attn_mma_kernel,
                         cudaFuncAttributeMaxDynamicSharedMemorySize, attn_smem);

    qkv_proj_mma<<<256, 256, proj_smem>>>(x, Wq, bq, Wk, bk, Wv, bv);
    attn_mma_kernel<<<dim3(16, 16), 256, attn_smem>>>(mask, Wo, bo, out);
}